// round 2
// baseline (speedup 1.0000x reference)
#include <cuda_runtime.h>
#include <cstdint>

// Problem constants
#define EDIM 2048
#define HNUM 16
#define NB   4
#define SLEN 2048
#define TLEN 2048
#define DHEAD 128

#define NEG_INF (__int_as_float(0xff800000))

// Scratch (allocation-free rule: __device__ globals)
__device__ float g_Q [(size_t)NB * SLEN * EDIM];            // 64 MB
__device__ float g_K [(size_t)NB * TLEN * EDIM];            // 64 MB
__device__ float g_V [(size_t)NB * TLEN * EDIM];            // 64 MB
__device__ float g_AO[(size_t)NB * SLEN * EDIM];            // 64 MB
__device__ float g_P [(size_t)NB * HNUM * SLEN * TLEN];     // 1 GB

// ---------------------------------------------------------------------------
// Generic tiled SGEMM.
//   TRANSB=1:  C[m][n] = sum_k A[m][k] * B[n][k]   (B is N x K row-major)
//   TRANSB=0:  C[m][n] = sum_k A[m][k] * B[k][n]   (B is K x N row-major)
// Optional bias[n], optional mask/scale epilogue:
//   v = v * scale;  if (mask[n*ldmask + m] == 0) v = -inf;
// Batched over blockIdx.z with (z/H, z%H) offsets.
// Requires: M,N % 128 == 0, K % 16 == 0.
// ---------------------------------------------------------------------------
template<bool TRANSB, bool HAS_BIAS, bool MASKED>
__global__ void __launch_bounds__(256)
gemm_kernel(const float* __restrict__ A, int lda, long sAn, long sAh,
            const float* __restrict__ B, int ldb, long sBn, long sBh,
            float*       __restrict__ C, int ldc, long sCn, long sCh,
            const float* __restrict__ bias,
            const int*   __restrict__ mask, int ldmask, float scale,
            int M, int N, int K, int H)
{
    const int z  = blockIdx.z;
    const int zn = z / H, zh = z % H;
    A += (size_t)zn * sAn + (size_t)zh * sAh;
    B += (size_t)zn * sBn + (size_t)zh * sBh;
    C += (size_t)zn * sCn + (size_t)zh * sCh;

    __shared__ float As[16][128];
    __shared__ float Bs[16][128];

    const int tid = threadIdx.x;
    const int m0  = blockIdx.y * 128;
    const int n0  = blockIdx.x * 128;

    const int tx = tid % 16;        // -> n
    const int ty = tid / 16;        // -> m

    // loader indices for K-contiguous tiles (A always; B when TRANSB)
    const int lrow = tid / 4;            // 0..63
    const int lkv  = (tid % 4) * 4;      // 0,4,8,12

    // loader indices for N-contiguous B tile (TRANSB=0)
    // 16 rows x 128 cols = 512 float4; each thread does 2
    float acc[8][8];
#pragma unroll
    for (int i = 0; i < 8; i++)
#pragma unroll
        for (int j = 0; j < 8; j++) acc[i][j] = 0.0f;

    for (int k0 = 0; k0 < K; k0 += 16) {
        // --- load A tile (transpose into As[k][m]) ---
#pragma unroll
        for (int i = 0; i < 2; i++) {
            int r = lrow + i * 64;
            float4 v = *(const float4*)(A + (size_t)(m0 + r) * lda + k0 + lkv);
            As[lkv + 0][r] = v.x; As[lkv + 1][r] = v.y;
            As[lkv + 2][r] = v.z; As[lkv + 3][r] = v.w;
        }
        // --- load B tile into Bs[k][n] ---
        if (TRANSB) {
#pragma unroll
            for (int i = 0; i < 2; i++) {
                int r = lrow + i * 64;
                float4 v = *(const float4*)(B + (size_t)(n0 + r) * ldb + k0 + lkv);
                Bs[lkv + 0][r] = v.x; Bs[lkv + 1][r] = v.y;
                Bs[lkv + 2][r] = v.z; Bs[lkv + 3][r] = v.w;
            }
        } else {
#pragma unroll
            for (int i = 0; i < 2; i++) {
                int f = tid + i * 256;       // 0..511
                int r = f / 32;              // k row 0..15
                int c = (f % 32) * 4;        // n col
                float4 v = *(const float4*)(B + (size_t)(k0 + r) * ldb + n0 + c);
                *(float4*)&Bs[r][c] = v;
            }
        }
        __syncthreads();

#pragma unroll
        for (int kk = 0; kk < 16; kk++) {
            float4 a0 = *(const float4*)&As[kk][ty * 8];
            float4 a1 = *(const float4*)&As[kk][ty * 8 + 4];
            float4 b0 = *(const float4*)&Bs[kk][tx * 8];
            float4 b1 = *(const float4*)&Bs[kk][tx * 8 + 4];
            float a[8] = {a0.x, a0.y, a0.z, a0.w, a1.x, a1.y, a1.z, a1.w};
            float b[8] = {b0.x, b0.y, b0.z, b0.w, b1.x, b1.y, b1.z, b1.w};
#pragma unroll
            for (int i = 0; i < 8; i++)
#pragma unroll
                for (int j = 0; j < 8; j++)
                    acc[i][j] = fmaf(a[i], b[j], acc[i][j]);
        }
        __syncthreads();
    }

    // --- epilogue ---
#pragma unroll
    for (int i = 0; i < 8; i++) {
        int m = m0 + ty * 8 + i;
#pragma unroll
        for (int j = 0; j < 8; j++) {
            int n = n0 + tx * 8 + j;
            float v = acc[i][j];
            if (HAS_BIAS) v += bias[n];
            if (MASKED) {
                v *= scale;
                if (mask[(size_t)n * ldmask + m] == 0) v = NEG_INF;
            }
            C[(size_t)m * ldc + n] = v;
        }
    }
}

// ---------------------------------------------------------------------------
// Row softmax over T (register-resident, one block per row)
// ---------------------------------------------------------------------------
__global__ void __launch_bounds__(256)
softmax_rows(float* __restrict__ P)
{
    const size_t row = blockIdx.x;
    float* p = P + row * (size_t)TLEN;
    const int tid = threadIdx.x;
    constexpr int PT = TLEN / 256;   // 8

    __shared__ float red[256];

    float r[PT];
    float m = NEG_INF;
#pragma unroll
    for (int i = 0; i < PT; i++) {
        r[i] = p[i * 256 + tid];
        m = fmaxf(m, r[i]);
    }
    red[tid] = m;
    __syncthreads();
#pragma unroll
    for (int s = 128; s > 0; s >>= 1) {
        if (tid < s) red[tid] = fmaxf(red[tid], red[tid + s]);
        __syncthreads();
    }
    m = red[0];
    __syncthreads();

    float sum = 0.0f;
#pragma unroll
    for (int i = 0; i < PT; i++) {
        r[i] = __expf(r[i] - m);
        sum += r[i];
    }
    red[tid] = sum;
    __syncthreads();
#pragma unroll
    for (int s = 128; s > 0; s >>= 1) {
        if (tid < s) red[tid] += red[tid + s];
        __syncthreads();
    }
    const float inv = 1.0f / red[0];
#pragma unroll
    for (int i = 0; i < PT; i++)
        p[i * 256 + tid] = r[i] * inv;
}

// ---------------------------------------------------------------------------
// Host launcher
// ---------------------------------------------------------------------------
extern "C" void kernel_launch(void* const* d_in, const int* in_sizes, int n_in,
                              void* d_out, int out_size)
{
    const float* query = (const float*)d_in[0];
    const float* key   = (const float*)d_in[1];
    const float* value = (const float*)d_in[2];
    const int*   amask = (const int*)  d_in[3];
    const float* Wq    = (const float*)d_in[4];
    const float* bq    = (const float*)d_in[5];
    const float* Wk    = (const float*)d_in[6];
    const float* bk    = (const float*)d_in[7];
    const float* Wv    = (const float*)d_in[8];
    const float* bv    = (const float*)d_in[9];
    const float* Wp    = (const float*)d_in[10];
    const float* bp    = (const float*)d_in[11];
    float* out = (float*)d_out;

    float *Qp, *Kp, *Vp, *Pp, *AOp;
    cudaGetSymbolAddress((void**)&Qp,  g_Q);
    cudaGetSymbolAddress((void**)&Kp,  g_K);
    cudaGetSymbolAddress((void**)&Vp,  g_V);
    cudaGetSymbolAddress((void**)&Pp,  g_P);
    cudaGetSymbolAddress((void**)&AOp, g_AO);

    const int M  = NB * SLEN;   // 8192
    const float scale = 1.0f / sqrtf((float)DHEAD);

    dim3 blk(256);
    dim3 gProj(EDIM / 128, M / 128, 1);          // 16 x 64

    // 1-3) Q, K, V projections: X @ W^T + b
    gemm_kernel<true, true, false><<<gProj, blk>>>(
        query, EDIM, 0, 0,  Wq, EDIM, 0, 0,  Qp, EDIM, 0, 0,
        bq, nullptr, 0, 0.0f, M, EDIM, EDIM, 1);
    gemm_kernel<true, true, false><<<gProj, blk>>>(
        key,   EDIM, 0, 0,  Wk, EDIM, 0, 0,  Kp, EDIM, 0, 0,
        bk, nullptr, 0, 0.0f, M, EDIM, EDIM, 1);
    gemm_kernel<true, true, false><<<gProj, blk>>>(
        value, EDIM, 0, 0,  Wv, EDIM, 0, 0,  Vp, EDIM, 0, 0,
        bv, nullptr, 0, 0.0f, M, EDIM, EDIM, 1);

    // 4) scores: P[bh][s][t] = (q_s . k_t) * scale, mask applied
    {
        dim3 g(TLEN / 128, SLEN / 128, NB * HNUM);   // 16 x 16 x 64
        gemm_kernel<true, false, true><<<g, blk>>>(
            Qp, EDIM, (long)SLEN * EDIM, DHEAD,
            Kp, EDIM, (long)TLEN * EDIM, DHEAD,
            Pp, TLEN, (long)HNUM * SLEN * TLEN, (long)SLEN * TLEN,
            nullptr, amask, SLEN, scale,
            SLEN, TLEN, DHEAD, HNUM);
    }

    // 5) softmax over t for every (bh, s) row
    softmax_rows<<<NB * HNUM * SLEN, blk>>>(Pp);

    // 6) AV: AO[n,s,h,:] = sum_t P[bh][s][t] * V[n,t,h,:]
    {
        dim3 g(DHEAD / 128, SLEN / 128, NB * HNUM);  // 1 x 16 x 64
        gemm_kernel<false, false, false><<<g, blk>>>(
            Pp, TLEN, (long)HNUM * SLEN * TLEN, (long)SLEN * TLEN,
            Vp, EDIM, (long)TLEN * EDIM, DHEAD,
            AOp, EDIM, (long)SLEN * EDIM, DHEAD,
            nullptr, nullptr, 0, 0.0f,
            SLEN, DHEAD, TLEN, HNUM);
    }

    // 7) output projection: out = AO @ Wp^T + bp
    gemm_kernel<true, true, false><<<gProj, blk>>>(
        AOp, EDIM, 0, 0,  Wp, EDIM, 0, 0,  out, EDIM, 0, 0,
        bp, nullptr, 0, 0.0f, M, EDIM, EDIM, 1);
}

// round 3
// speedup vs baseline: 2.7734x; 2.7734x over previous
#include <cuda_runtime.h>
#include <cstdint>

// Problem constants
#define EDIM 2048
#define HNUM 16
#define NB   4
#define SLEN 2048
#define TLEN 2048
#define DHEAD 128

#define NEG_INF (__int_as_float(0xff800000))

// Scratch (allocation-free rule: __device__ globals)
__device__ float g_Q [(size_t)NB * SLEN * EDIM];            // 64 MB
__device__ float g_K [(size_t)NB * TLEN * EDIM];            // 64 MB
__device__ float g_V [(size_t)NB * TLEN * EDIM];            // 64 MB
__device__ float g_AO[(size_t)NB * SLEN * EDIM];            // 64 MB
__device__ float g_P [(size_t)NB * HNUM * SLEN * TLEN];     // 1 GB

// fp32 -> tf32 with round-to-nearest (keeps eps ~ 2^-11)
__device__ __forceinline__ uint32_t f2tf(float f) {
    uint32_t u;
    asm("cvt.rna.tf32.f32 %0, %1;" : "=r"(u) : "f"(f));
    return u;
}

__device__ __forceinline__ void mma8(float& c0, float& c1, float& c2, float& c3,
                                     uint32_t a0, uint32_t a1, uint32_t a2, uint32_t a3,
                                     uint32_t b0, uint32_t b1) {
    asm volatile(
        "mma.sync.aligned.m16n8k8.row.col.f32.tf32.tf32.f32 "
        "{%0,%1,%2,%3},{%4,%5,%6,%7},{%8,%9},{%0,%1,%2,%3};"
        : "+f"(c0), "+f"(c1), "+f"(c2), "+f"(c3)
        : "r"(a0), "r"(a1), "r"(a2), "r"(a3), "r"(b0), "r"(b1));
}

// ---------------------------------------------------------------------------
// Tensor-core tf32 GEMM, 128x128 CTA tile, kChunk=16, 256 threads.
//   TRANSB=1:  C[m][n] = sum_k A[m][k] * B[n][k]
//   TRANSB=0:  C[m][n] = sum_k A[m][k] * B[k][n]
// Optional bias[n]; optional mask epilogue (v*=scale; mask[n*ldmask+m]==0 -> -inf)
// Requires M,N multiples of 128 (via grid), K multiple of 16.
// ---------------------------------------------------------------------------
#define ASTRIDE 20    // [m][k] row stride (words) -> conflict-free frag reads
#define BSTRIDE_NN 136 // [k][n] row stride (words) for NN B tile

template<bool TRANSB, bool HAS_BIAS, bool MASKED>
__global__ void __launch_bounds__(256, 2)
gemm_tc(const float* __restrict__ A, int lda, long sAn, long sAh,
        const float* __restrict__ B, int ldb, long sBn, long sBh,
        float*       __restrict__ C, int ldc, long sCn, long sCh,
        const float* __restrict__ bias,
        const int*   __restrict__ mask, int ldmask, float scale,
        int K, int H)
{
    const int z  = blockIdx.z;
    const int zn = z / H, zh = z % H;
    A += (size_t)zn * sAn + (size_t)zh * sAh;
    B += (size_t)zn * sBn + (size_t)zh * sBh;
    C += (size_t)zn * sCn + (size_t)zh * sCh;

    // A tile: [m=128][k=16] stride 20.  B tile: TRANSB -> [n=128][k=16] stride 20
    //                                           NN     -> [k=16][n=128] stride 136
    __shared__ uint32_t As[2][128 * ASTRIDE];
    __shared__ uint32_t Bs[2][128 * ASTRIDE];   // 2560 words >= 16*136=2176

    const int tid  = threadIdx.x;
    const int lane = tid & 31;
    const int warp = tid >> 5;
    const int wm   = warp & 3;     // 4 warps along m (32 rows each)
    const int wn   = warp >> 2;    // 2 warps along n (64 cols each)
    const int m0   = blockIdx.y * 128;
    const int n0   = blockIdx.x * 128;

    const int lr = tid >> 2;           // 0..63 (row loader)
    const int lk = (tid & 3) << 2;     // 0,4,8,12

    const int g = lane >> 2;           // fragment group (row)
    const int t = lane & 3;            // fragment thread-in-group

    float acc[2][8][4];
#pragma unroll
    for (int i = 0; i < 2; i++)
#pragma unroll
        for (int j = 0; j < 8; j++)
#pragma unroll
            for (int q = 0; q < 4; q++) acc[i][j][q] = 0.0f;

    const int nch = K >> 4;

    // ---- initial tile load (chunk 0) ----
#pragma unroll
    for (int i = 0; i < 2; i++) {
        int r = lr + i * 64;
        float4 v = *(const float4*)(A + (size_t)(m0 + r) * lda + lk);
        uint32_t* d = &As[0][r * ASTRIDE + lk];
        d[0] = f2tf(v.x); d[1] = f2tf(v.y); d[2] = f2tf(v.z); d[3] = f2tf(v.w);
    }
    if (TRANSB) {
#pragma unroll
        for (int i = 0; i < 2; i++) {
            int r = lr + i * 64;
            float4 v = *(const float4*)(B + (size_t)(n0 + r) * ldb + lk);
            uint32_t* d = &Bs[0][r * ASTRIDE + lk];
            d[0] = f2tf(v.x); d[1] = f2tf(v.y); d[2] = f2tf(v.z); d[3] = f2tf(v.w);
        }
    } else {
#pragma unroll
        for (int i = 0; i < 2; i++) {
            int f = tid + i * 256;
            int r = f >> 5;            // k row 0..15
            int c = (f & 31) << 2;     // n col
            float4 v = *(const float4*)(B + (size_t)r * ldb + n0 + c);
            uint32_t* d = &Bs[0][r * BSTRIDE_NN + c];
            d[0] = f2tf(v.x); d[1] = f2tf(v.y); d[2] = f2tf(v.z); d[3] = f2tf(v.w);
        }
    }
    __syncthreads();

    int buf = 0;
    for (int ch = 0; ch < nch; ch++) {
        const bool nxt = (ch + 1 < nch);
        const int  k1  = (ch + 1) << 4;

        float4 ra[2], rb[2];
        if (nxt) {
#pragma unroll
            for (int i = 0; i < 2; i++) {
                int r = lr + i * 64;
                ra[i] = *(const float4*)(A + (size_t)(m0 + r) * lda + k1 + lk);
            }
            if (TRANSB) {
#pragma unroll
                for (int i = 0; i < 2; i++) {
                    int r = lr + i * 64;
                    rb[i] = *(const float4*)(B + (size_t)(n0 + r) * ldb + k1 + lk);
                }
            } else {
#pragma unroll
                for (int i = 0; i < 2; i++) {
                    int f = tid + i * 256;
                    int r = f >> 5;
                    int c = (f & 31) << 2;
                    rb[i] = *(const float4*)(B + (size_t)(k1 + r) * ldb + n0 + c);
                }
            }
        }

        // ---- compute on current buffer ----
        const uint32_t* as = As[buf];
        const uint32_t* bs = Bs[buf];
#pragma unroll
        for (int ks = 0; ks < 16; ks += 8) {
            uint32_t af[2][4];
#pragma unroll
            for (int mi = 0; mi < 2; mi++) {
                int row = wm * 32 + mi * 16 + g;
                af[mi][0] = as[row * ASTRIDE + ks + t];
                af[mi][1] = as[(row + 8) * ASTRIDE + ks + t];
                af[mi][2] = as[row * ASTRIDE + ks + t + 4];
                af[mi][3] = as[(row + 8) * ASTRIDE + ks + t + 4];
            }
            uint32_t bf[8][2];
#pragma unroll
            for (int ni = 0; ni < 8; ni++) {
                int nn = wn * 64 + ni * 8 + g;
                if (TRANSB) {
                    bf[ni][0] = bs[nn * ASTRIDE + ks + t];
                    bf[ni][1] = bs[nn * ASTRIDE + ks + t + 4];
                } else {
                    bf[ni][0] = bs[(ks + t) * BSTRIDE_NN + nn];
                    bf[ni][1] = bs[(ks + t + 4) * BSTRIDE_NN + nn];
                }
            }
#pragma unroll
            for (int mi = 0; mi < 2; mi++)
#pragma unroll
                for (int ni = 0; ni < 8; ni++)
                    mma8(acc[mi][ni][0], acc[mi][ni][1], acc[mi][ni][2], acc[mi][ni][3],
                         af[mi][0], af[mi][1], af[mi][2], af[mi][3],
                         bf[ni][0], bf[ni][1]);
        }

        // ---- store prefetched tile into other buffer ----
        if (nxt) {
            uint32_t* asn = As[buf ^ 1];
            uint32_t* bsn = Bs[buf ^ 1];
#pragma unroll
            for (int i = 0; i < 2; i++) {
                int r = lr + i * 64;
                uint32_t* d = &asn[r * ASTRIDE + lk];
                d[0] = f2tf(ra[i].x); d[1] = f2tf(ra[i].y);
                d[2] = f2tf(ra[i].z); d[3] = f2tf(ra[i].w);
            }
            if (TRANSB) {
#pragma unroll
                for (int i = 0; i < 2; i++) {
                    int r = lr + i * 64;
                    uint32_t* d = &bsn[r * ASTRIDE + lk];
                    d[0] = f2tf(rb[i].x); d[1] = f2tf(rb[i].y);
                    d[2] = f2tf(rb[i].z); d[3] = f2tf(rb[i].w);
                }
            } else {
#pragma unroll
                for (int i = 0; i < 2; i++) {
                    int f = tid + i * 256;
                    int r = f >> 5;
                    int c = (f & 31) << 2;
                    uint32_t* d = &bsn[r * BSTRIDE_NN + c];
                    d[0] = f2tf(rb[i].x); d[1] = f2tf(rb[i].y);
                    d[2] = f2tf(rb[i].z); d[3] = f2tf(rb[i].w);
                }
            }
        }
        __syncthreads();
        buf ^= 1;
    }

    // ---- epilogue ----
#pragma unroll
    for (int mi = 0; mi < 2; mi++) {
#pragma unroll
        for (int rr = 0; rr < 2; rr++) {
            int m = m0 + wm * 32 + mi * 16 + g + rr * 8;
#pragma unroll
            for (int ni = 0; ni < 8; ni++) {
                int n = n0 + wn * 64 + ni * 8 + 2 * t;
                float v0 = acc[mi][ni][rr * 2 + 0];
                float v1 = acc[mi][ni][rr * 2 + 1];
                if (HAS_BIAS) { v0 += bias[n]; v1 += bias[n + 1]; }
                if (MASKED) {
                    v0 *= scale; v1 *= scale;
                    if (mask[(size_t)n * ldmask + m] == 0)       v0 = NEG_INF;
                    if (mask[(size_t)(n + 1) * ldmask + m] == 0) v1 = NEG_INF;
                }
                *(float2*)(C + (size_t)m * ldc + n) = make_float2(v0, v1);
            }
        }
    }
}

// ---------------------------------------------------------------------------
// Row softmax over T (register-resident, one block per row)
// ---------------------------------------------------------------------------
__global__ void __launch_bounds__(256)
softmax_rows(float* __restrict__ P)
{
    const size_t row = blockIdx.x;
    float* p = P + row * (size_t)TLEN;
    const int tid = threadIdx.x;
    constexpr int PT = TLEN / 256;   // 8

    __shared__ float red[256];

    float r[PT];
    float m = NEG_INF;
#pragma unroll
    for (int i = 0; i < PT; i++) {
        r[i] = p[i * 256 + tid];
        m = fmaxf(m, r[i]);
    }
    red[tid] = m;
    __syncthreads();
#pragma unroll
    for (int s = 128; s > 0; s >>= 1) {
        if (tid < s) red[tid] = fmaxf(red[tid], red[tid + s]);
        __syncthreads();
    }
    m = red[0];
    __syncthreads();

    float sum = 0.0f;
#pragma unroll
    for (int i = 0; i < PT; i++) {
        r[i] = __expf(r[i] - m);
        sum += r[i];
    }
    red[tid] = sum;
    __syncthreads();
#pragma unroll
    for (int s = 128; s > 0; s >>= 1) {
        if (tid < s) red[tid] += red[tid + s];
        __syncthreads();
    }
    const float inv = 1.0f / red[0];
#pragma unroll
    for (int i = 0; i < PT; i++)
        p[i * 256 + tid] = r[i] * inv;
}

// ---------------------------------------------------------------------------
// Host launcher
// ---------------------------------------------------------------------------
extern "C" void kernel_launch(void* const* d_in, const int* in_sizes, int n_in,
                              void* d_out, int out_size)
{
    const float* query = (const float*)d_in[0];
    const float* key   = (const float*)d_in[1];
    const float* value = (const float*)d_in[2];
    const int*   amask = (const int*)  d_in[3];
    const float* Wq    = (const float*)d_in[4];
    const float* bq    = (const float*)d_in[5];
    const float* Wk    = (const float*)d_in[6];
    const float* bk    = (const float*)d_in[7];
    const float* Wv    = (const float*)d_in[8];
    const float* bv    = (const float*)d_in[9];
    const float* Wp    = (const float*)d_in[10];
    const float* bp    = (const float*)d_in[11];
    float* out = (float*)d_out;

    float *Qp, *Kp, *Vp, *Pp, *AOp;
    cudaGetSymbolAddress((void**)&Qp,  g_Q);
    cudaGetSymbolAddress((void**)&Kp,  g_K);
    cudaGetSymbolAddress((void**)&Vp,  g_V);
    cudaGetSymbolAddress((void**)&Pp,  g_P);
    cudaGetSymbolAddress((void**)&AOp, g_AO);

    const int M = NB * SLEN;   // 8192
    const float scale = 1.0f / sqrtf((float)DHEAD);

    dim3 blk(256);
    dim3 gProj(EDIM / 128, M / 128, 1);          // 16 x 64

    // 1-3) Q, K, V projections: X @ W^T + b
    gemm_tc<true, true, false><<<gProj, blk>>>(
        query, EDIM, 0, 0,  Wq, EDIM, 0, 0,  Qp, EDIM, 0, 0,
        bq, nullptr, 0, 0.0f, EDIM, 1);
    gemm_tc<true, true, false><<<gProj, blk>>>(
        key,   EDIM, 0, 0,  Wk, EDIM, 0, 0,  Kp, EDIM, 0, 0,
        bk, nullptr, 0, 0.0f, EDIM, 1);
    gemm_tc<true, true, false><<<gProj, blk>>>(
        value, EDIM, 0, 0,  Wv, EDIM, 0, 0,  Vp, EDIM, 0, 0,
        bv, nullptr, 0, 0.0f, EDIM, 1);

    // 4) scores: P[bh][s][t] = (q_s . k_t) * scale, mask applied
    {
        dim3 g(TLEN / 128, SLEN / 128, NB * HNUM);   // 16 x 16 x 64
        gemm_tc<true, false, true><<<g, blk>>>(
            Qp, EDIM, (long)SLEN * EDIM, DHEAD,
            Kp, EDIM, (long)TLEN * EDIM, DHEAD,
            Pp, TLEN, (long)HNUM * SLEN * TLEN, (long)SLEN * TLEN,
            nullptr, amask, SLEN, scale,
            DHEAD, HNUM);
    }

    // 5) softmax over t for every (bh, s) row
    softmax_rows<<<NB * HNUM * SLEN, blk>>>(Pp);

    // 6) AV: AO[n,s,h,:] = sum_t P[bh][s][t] * V[n,t,h,:]
    {
        dim3 g(DHEAD / 128, SLEN / 128, NB * HNUM);  // 1 x 16 x 64
        gemm_tc<false, false, false><<<g, blk>>>(
            Pp, TLEN, (long)HNUM * SLEN * TLEN, (long)SLEN * TLEN,
            Vp, EDIM, (long)TLEN * EDIM, DHEAD,
            AOp, EDIM, (long)SLEN * EDIM, DHEAD,
            nullptr, nullptr, 0, 0.0f,
            TLEN, HNUM);
    }

    // 7) output projection: out = AO @ Wp^T + bp
    gemm_tc<true, true, false><<<gProj, blk>>>(
        AOp, EDIM, 0, 0,  Wp, EDIM, 0, 0,  out, EDIM, 0, 0,
        bp, nullptr, 0, 0.0f, EDIM, 1);
}

// round 7
// speedup vs baseline: 3.4112x; 1.2300x over previous
#include <cuda_runtime.h>
#include <cstdint>

// Problem constants
#define EDIM 2048
#define HNUM 16
#define NB   4
#define SLEN 2048
#define TLEN 2048
#define DHEAD 128

#define NEG_INF (__int_as_float(0xff800000))

// Scratch (allocation-free rule: __device__ globals)
__device__ float g_Q [(size_t)NB * SLEN * EDIM];            // 64 MB (tf32-rounded)
__device__ float g_K [(size_t)NB * TLEN * EDIM];            // 64 MB (tf32-rounded)
__device__ float g_V [(size_t)NB * TLEN * EDIM];            // 64 MB (tf32-rounded)
__device__ float g_AO[(size_t)NB * SLEN * EDIM];            // 64 MB

// fp32 -> tf32 round-to-nearest
__device__ __forceinline__ uint32_t f2tf(float f) {
    uint32_t u;
    asm("cvt.rna.tf32.f32 %0, %1;" : "=r"(u) : "f"(f));
    return u;
}

__device__ __forceinline__ void mma8(float& c0, float& c1, float& c2, float& c3,
                                     uint32_t a0, uint32_t a1, uint32_t a2, uint32_t a3,
                                     uint32_t b0, uint32_t b1) {
    asm volatile(
        "mma.sync.aligned.m16n8k8.row.col.f32.tf32.tf32.f32 "
        "{%0,%1,%2,%3},{%4,%5,%6,%7},{%8,%9},{%0,%1,%2,%3};"
        : "+f"(c0), "+f"(c1), "+f"(c2), "+f"(c3)
        : "r"(a0), "r"(a1), "r"(a2), "r"(a3), "r"(b0), "r"(b1));
}

__device__ __forceinline__ uint32_t smem_u32(const void* p) {
    uint32_t a;
    asm("{ .reg .u64 t; cvta.to.shared.u64 t, %1; cvt.u32.u64 %0, t; }" : "=r"(a) : "l"(p));
    return a;
}
__device__ __forceinline__ void cp16(uint32_t dst, const void* src) {
    asm volatile("cp.async.cg.shared.global [%0], [%1], 16;" :: "r"(dst), "l"(src));
}

// ---------------------------------------------------------------------------
// Tensor-core tf32 GEMM (TRANSB form only): C[m][n] = sum_k A[m][k]*B[n][k]
// 128x128 CTA tile, kChunk=16, 256 threads, double-buffered SMEM.
// RND: store C rounded to tf32 (for Q/K/V so the fused kernel can stream raw).
// ---------------------------------------------------------------------------
#define ASTRIDE 20

template<bool HAS_BIAS, bool RND>
__global__ void __launch_bounds__(256, 2)
gemm_tc(const float* __restrict__ A, int lda,
        const float* __restrict__ B, int ldb,
        float*       __restrict__ C, int ldc,
        const float* __restrict__ bias, int K)
{
    __shared__ uint32_t As[2][128 * ASTRIDE];
    __shared__ uint32_t Bs[2][128 * ASTRIDE];

    const int tid  = threadIdx.x;
    const int lane = tid & 31;
    const int warp = tid >> 5;
    const int wm   = warp & 3;
    const int wn   = warp >> 2;
    const int m0   = blockIdx.y * 128;
    const int n0   = blockIdx.x * 128;

    const int lr = tid >> 2;
    const int lk = (tid & 3) << 2;
    const int g  = lane >> 2;
    const int t  = lane & 3;

    float acc[2][8][4];
#pragma unroll
    for (int i = 0; i < 2; i++)
#pragma unroll
        for (int j = 0; j < 8; j++)
#pragma unroll
            for (int q = 0; q < 4; q++) acc[i][j][q] = 0.0f;

    const int nch = K >> 4;

#pragma unroll
    for (int i = 0; i < 2; i++) {
        int r = lr + i * 64;
        float4 v = *(const float4*)(A + (size_t)(m0 + r) * lda + lk);
        uint32_t* d = &As[0][r * ASTRIDE + lk];
        d[0] = f2tf(v.x); d[1] = f2tf(v.y); d[2] = f2tf(v.z); d[3] = f2tf(v.w);
        float4 w = *(const float4*)(B + (size_t)(n0 + r) * ldb + lk);
        uint32_t* e = &Bs[0][r * ASTRIDE + lk];
        e[0] = f2tf(w.x); e[1] = f2tf(w.y); e[2] = f2tf(w.z); e[3] = f2tf(w.w);
    }
    __syncthreads();

    int buf = 0;
    for (int ch = 0; ch < nch; ch++) {
        const bool nxt = (ch + 1 < nch);
        const int  k1  = (ch + 1) << 4;

        float4 ra[2], rb[2];
        if (nxt) {
#pragma unroll
            for (int i = 0; i < 2; i++) {
                int r = lr + i * 64;
                ra[i] = *(const float4*)(A + (size_t)(m0 + r) * lda + k1 + lk);
                rb[i] = *(const float4*)(B + (size_t)(n0 + r) * ldb + k1 + lk);
            }
        }

        const uint32_t* as = As[buf];
        const uint32_t* bs = Bs[buf];
#pragma unroll
        for (int ks = 0; ks < 16; ks += 8) {
            uint32_t af[2][4];
#pragma unroll
            for (int mi = 0; mi < 2; mi++) {
                int row = wm * 32 + mi * 16 + g;
                af[mi][0] = as[row * ASTRIDE + ks + t];
                af[mi][1] = as[(row + 8) * ASTRIDE + ks + t];
                af[mi][2] = as[row * ASTRIDE + ks + t + 4];
                af[mi][3] = as[(row + 8) * ASTRIDE + ks + t + 4];
            }
            uint32_t bf[8][2];
#pragma unroll
            for (int ni = 0; ni < 8; ni++) {
                int nn = wn * 64 + ni * 8 + g;
                bf[ni][0] = bs[nn * ASTRIDE + ks + t];
                bf[ni][1] = bs[nn * ASTRIDE + ks + t + 4];
            }
#pragma unroll
            for (int mi = 0; mi < 2; mi++)
#pragma unroll
                for (int ni = 0; ni < 8; ni++)
                    mma8(acc[mi][ni][0], acc[mi][ni][1], acc[mi][ni][2], acc[mi][ni][3],
                         af[mi][0], af[mi][1], af[mi][2], af[mi][3],
                         bf[ni][0], bf[ni][1]);
        }

        if (nxt) {
            uint32_t* asn = As[buf ^ 1];
            uint32_t* bsn = Bs[buf ^ 1];
#pragma unroll
            for (int i = 0; i < 2; i++) {
                int r = lr + i * 64;
                uint32_t* d = &asn[r * ASTRIDE + lk];
                d[0] = f2tf(ra[i].x); d[1] = f2tf(ra[i].y);
                d[2] = f2tf(ra[i].z); d[3] = f2tf(ra[i].w);
                uint32_t* e = &bsn[r * ASTRIDE + lk];
                e[0] = f2tf(rb[i].x); e[1] = f2tf(rb[i].y);
                e[2] = f2tf(rb[i].z); e[3] = f2tf(rb[i].w);
            }
        }
        __syncthreads();
        buf ^= 1;
    }

#pragma unroll
    for (int mi = 0; mi < 2; mi++) {
#pragma unroll
        for (int rr = 0; rr < 2; rr++) {
            int m = m0 + wm * 32 + mi * 16 + g + rr * 8;
#pragma unroll
            for (int ni = 0; ni < 8; ni++) {
                int n = n0 + wn * 64 + ni * 8 + 2 * t;
                float v0 = acc[mi][ni][rr * 2 + 0];
                float v1 = acc[mi][ni][rr * 2 + 1];
                if (HAS_BIAS) { v0 += bias[n]; v1 += bias[n + 1]; }
                if (RND) {
                    v0 = __uint_as_float(f2tf(v0));
                    v1 = __uint_as_float(f2tf(v1));
                }
                *(float2*)(C + (size_t)m * ldc + n) = make_float2(v0, v1);
            }
        }
    }
}

// ---------------------------------------------------------------------------
// Fused flash attention: per CTA 128 query rows; stream K/V in T-tiles of 64.
//   S = Q K^T * scale (+mask) ; online softmax ; O += P V ; AO = O / l
// Inputs g_Q/g_K/g_V are already tf32-rounded -> raw cp.async feeds MMA.
// SMEM word layout (uint32):
//   Qs [128][132]  A-layout  (Q)
//   Ks [ 64][132]  B-layout  ([t][d])
//   Vs [2][64][136] NN-layout ([t][d] used as B[k=t][n=d]), double buffered
//   Ps [128][ 68]  A-layout  ([s][t])
//   red_m [128][2], red_s [128][2]
// ---------------------------------------------------------------------------
#define BT 64
#define LDQ 132
#define LDK 132
#define LDV 136
#define LDP 68
#define OFF_Q 0
#define OFF_K 16896
#define OFF_V 25344
#define VBUFW 8704
#define OFF_P 42752
#define OFF_RM 51456
#define OFF_RS 51712
#define SMEM_WORDS 51968

__global__ void __launch_bounds__(256, 1)
attn_fused(const float* __restrict__ Q, const float* __restrict__ K,
           const float* __restrict__ V, const int* __restrict__ mask,
           float* __restrict__ AO)
{
    extern __shared__ uint32_t sm[];
    const uint32_t smb = smem_u32(sm);

    const int tid  = threadIdx.x;
    const int lane = tid & 31;
    const int warp = tid >> 5;
    const int wm   = warp & 3;
    const int wn   = warp >> 2;
    const int g    = lane >> 2;
    const int t    = lane & 3;
    const int s0   = blockIdx.x * 128;
    const int bh   = blockIdx.y;
    const int zn   = bh >> 4, zh = bh & 15;
    const float scale = 0.08838834764831845f;   // 1/sqrt(128)

    const size_t qbase  = ((size_t)zn * SLEN + s0) * EDIM + (size_t)zh * DHEAD;
    const size_t kvbase = ((size_t)zn * TLEN) * EDIM + (size_t)zh * DHEAD;

    // ---- prologue: Q (once), K0, V0 ----
#pragma unroll
    for (int i = 0; i < 16; i++) {
        int idx = tid + i * 256;
        int r = idx >> 5, c = (idx & 31) << 2;
        cp16(smb + (OFF_Q + r * LDQ + c) * 4, Q + qbase + (size_t)r * EDIM + c);
    }
#pragma unroll
    for (int i = 0; i < 8; i++) {
        int idx = tid + i * 256;
        int r = idx >> 5, c = (idx & 31) << 2;
        cp16(smb + (OFF_K + r * LDK + c) * 4, K + kvbase + (size_t)r * EDIM + c);
    }
#pragma unroll
    for (int i = 0; i < 8; i++) {
        int idx = tid + i * 256;
        int r = idx >> 5, c = (idx & 31) << 2;
        cp16(smb + (OFF_V + r * LDV + c) * 4, V + kvbase + (size_t)r * EDIM + c);
    }
    asm volatile("cp.async.commit_group;");

    float Oa[2][8][4];
#pragma unroll
    for (int i = 0; i < 2; i++)
#pragma unroll
        for (int j = 0; j < 8; j++)
#pragma unroll
            for (int q = 0; q < 4; q++) Oa[i][j][q] = 0.0f;
    float m_run[4], l_run[4];
#pragma unroll
    for (int s = 0; s < 4; s++) { m_run[s] = NEG_INF; l_run[s] = 0.0f; }

    const int arow0 = wm * 32;

    for (int j = 0; j < TLEN / BT; j++) {
        asm volatile("cp.async.wait_group 0;" ::: "memory");
        __syncthreads();
        const int vb = j & 1;
        const int t0 = j * BT;

        // ---- S = Q K^T ----
        float Sa[2][4][4];
#pragma unroll
        for (int i = 0; i < 2; i++)
#pragma unroll
            for (int n = 0; n < 4; n++)
#pragma unroll
                for (int q = 0; q < 4; q++) Sa[i][n][q] = 0.0f;

#pragma unroll
        for (int ks = 0; ks < DHEAD; ks += 8) {
            uint32_t af[2][4];
#pragma unroll
            for (int mi = 0; mi < 2; mi++) {
                int row = arow0 + mi * 16 + g;
                af[mi][0] = sm[OFF_Q + row * LDQ + ks + t];
                af[mi][1] = sm[OFF_Q + (row + 8) * LDQ + ks + t];
                af[mi][2] = sm[OFF_Q + row * LDQ + ks + t + 4];
                af[mi][3] = sm[OFF_Q + (row + 8) * LDQ + ks + t + 4];
            }
            uint32_t bf[4][2];
#pragma unroll
            for (int ni = 0; ni < 4; ni++) {
                int n = wn * 32 + ni * 8 + g;
                bf[ni][0] = sm[OFF_K + n * LDK + ks + t];
                bf[ni][1] = sm[OFF_K + n * LDK + ks + t + 4];
            }
#pragma unroll
            for (int mi = 0; mi < 2; mi++)
#pragma unroll
                for (int ni = 0; ni < 4; ni++)
                    mma8(Sa[mi][ni][0], Sa[mi][ni][1], Sa[mi][ni][2], Sa[mi][ni][3],
                         af[mi][0], af[mi][1], af[mi][2], af[mi][3],
                         bf[ni][0], bf[ni][1]);
        }

        // ---- scale + mask ----
#pragma unroll
        for (int mi = 0; mi < 2; mi++)
#pragma unroll
            for (int rr = 0; rr < 2; rr++) {
                int srow = s0 + arow0 + mi * 16 + rr * 8 + g;
#pragma unroll
                for (int ni = 0; ni < 4; ni++)
#pragma unroll
                    for (int q = 0; q < 2; q++) {
                        int col = t0 + wn * 32 + ni * 8 + 2 * t + q;
                        float v = Sa[mi][ni][rr * 2 + q] * scale;
                        if (__ldg(&mask[(size_t)col * SLEN + srow]) == 0) v = NEG_INF;
                        Sa[mi][ni][rr * 2 + q] = v;
                    }
            }

        // ---- row max ----
#pragma unroll
        for (int mi = 0; mi < 2; mi++)
#pragma unroll
            for (int rr = 0; rr < 2; rr++) {
                float mx = NEG_INF;
#pragma unroll
                for (int ni = 0; ni < 4; ni++) {
                    mx = fmaxf(mx, Sa[mi][ni][rr * 2]);
                    mx = fmaxf(mx, Sa[mi][ni][rr * 2 + 1]);
                }
                mx = fmaxf(mx, __shfl_xor_sync(0xffffffffu, mx, 1));
                mx = fmaxf(mx, __shfl_xor_sync(0xffffffffu, mx, 2));
                if (t == 0) {
                    int r = arow0 + mi * 16 + rr * 8 + g;
                    *(float*)&sm[OFF_RM + r * 2 + wn] = mx;
                }
            }
        __syncthreads();

        float m_new[4], alpha[4];
#pragma unroll
        for (int mi = 0; mi < 2; mi++)
#pragma unroll
            for (int rr = 0; rr < 2; rr++) {
                int s = mi * 2 + rr;
                int r = arow0 + mi * 16 + rr * 8 + g;
                float tm = fmaxf(*(float*)&sm[OFF_RM + r * 2],
                                 *(float*)&sm[OFF_RM + r * 2 + 1]);
                m_new[s] = fmaxf(m_run[s], tm);
                alpha[s] = __expf(m_run[s] - m_new[s]);
                m_run[s] = m_new[s];
            }

        // ---- P = exp(S - m), write to SMEM, row sums ----
#pragma unroll
        for (int mi = 0; mi < 2; mi++)
#pragma unroll
            for (int rr = 0; rr < 2; rr++) {
                int s = mi * 2 + rr;
                int r = arow0 + mi * 16 + rr * 8 + g;
                float sum = 0.0f;
#pragma unroll
                for (int ni = 0; ni < 4; ni++) {
                    float p0 = __expf(Sa[mi][ni][rr * 2]     - m_new[s]);
                    float p1 = __expf(Sa[mi][ni][rr * 2 + 1] - m_new[s]);
                    sum += p0 + p1;
                    uint2 pp = make_uint2(f2tf(p0), f2tf(p1));
                    *(uint2*)&sm[OFF_P + r * LDP + wn * 32 + ni * 8 + 2 * t] = pp;
                }
                sum += __shfl_xor_sync(0xffffffffu, sum, 1);
                sum += __shfl_xor_sync(0xffffffffu, sum, 2);
                if (t == 0) *(float*)&sm[OFF_RS + r * 2 + wn] = sum;
            }
        __syncthreads();

#pragma unroll
        for (int mi = 0; mi < 2; mi++)
#pragma unroll
            for (int rr = 0; rr < 2; rr++) {
                int s = mi * 2 + rr;
                int r = arow0 + mi * 16 + rr * 8 + g;
                float ts = *(float*)&sm[OFF_RS + r * 2] + *(float*)&sm[OFF_RS + r * 2 + 1];
                l_run[s] = l_run[s] * alpha[s] + ts;
            }
        // rescale O
#pragma unroll
        for (int mi = 0; mi < 2; mi++)
#pragma unroll
            for (int ni = 0; ni < 8; ni++)
#pragma unroll
                for (int q = 0; q < 4; q++)
                    Oa[mi][ni][q] *= alpha[mi * 2 + (q >> 1)];

        // ---- prefetch next K/V tile (overlaps with PV) ----
        if (j + 1 < TLEN / BT) {
            const int tn = (j + 1) * BT;
            const int vn = vb ^ 1;
#pragma unroll
            for (int i = 0; i < 8; i++) {
                int idx = tid + i * 256;
                int r = idx >> 5, c = (idx & 31) << 2;
                cp16(smb + (OFF_K + r * LDK + c) * 4,
                     K + kvbase + (size_t)(tn + r) * EDIM + c);
            }
#pragma unroll
            for (int i = 0; i < 8; i++) {
                int idx = tid + i * 256;
                int r = idx >> 5, c = (idx & 31) << 2;
                cp16(smb + (OFF_V + vn * VBUFW + r * LDV + c) * 4,
                     V + kvbase + (size_t)(tn + r) * EDIM + c);
            }
            asm volatile("cp.async.commit_group;");
        }

        // ---- O += P V ----
        const uint32_t* vs = &sm[OFF_V + vb * VBUFW];
#pragma unroll
        for (int ks = 0; ks < BT; ks += 8) {
            uint32_t af[2][4];
#pragma unroll
            for (int mi = 0; mi < 2; mi++) {
                int row = arow0 + mi * 16 + g;
                af[mi][0] = sm[OFF_P + row * LDP + ks + t];
                af[mi][1] = sm[OFF_P + (row + 8) * LDP + ks + t];
                af[mi][2] = sm[OFF_P + row * LDP + ks + t + 4];
                af[mi][3] = sm[OFF_P + (row + 8) * LDP + ks + t + 4];
            }
            uint32_t bf[8][2];
#pragma unroll
            for (int ni = 0; ni < 8; ni++) {
                int n = wn * 64 + ni * 8 + g;
                bf[ni][0] = vs[(ks + t) * LDV + n];
                bf[ni][1] = vs[(ks + t + 4) * LDV + n];
            }
#pragma unroll
            for (int mi = 0; mi < 2; mi++)
#pragma unroll
                for (int ni = 0; ni < 8; ni++)
                    mma8(Oa[mi][ni][0], Oa[mi][ni][1], Oa[mi][ni][2], Oa[mi][ni][3],
                         af[mi][0], af[mi][1], af[mi][2], af[mi][3],
                         bf[ni][0], bf[ni][1]);
        }
    }

    // ---- epilogue: AO = O / l ----
#pragma unroll
    for (int mi = 0; mi < 2; mi++)
#pragma unroll
        for (int rr = 0; rr < 2; rr++) {
            int s = mi * 2 + rr;
            float inv = 1.0f / l_run[s];
            int r = arow0 + mi * 16 + rr * 8 + g;
#pragma unroll
            for (int ni = 0; ni < 8; ni++) {
                int col = wn * 64 + ni * 8 + 2 * t;
                float2 o = make_float2(Oa[mi][ni][rr * 2] * inv,
                                       Oa[mi][ni][rr * 2 + 1] * inv);
                *(float2*)(AO + qbase + (size_t)r * EDIM + col) = o;
            }
        }
}

// ---------------------------------------------------------------------------
// Host launcher
// ---------------------------------------------------------------------------
extern "C" void kernel_launch(void* const* d_in, const int* in_sizes, int n_in,
                              void* d_out, int out_size)
{
    const float* query = (const float*)d_in[0];
    const float* key   = (const float*)d_in[1];
    const float* value = (const float*)d_in[2];
    const int*   amask = (const int*)  d_in[3];
    const float* Wq    = (const float*)d_in[4];
    const float* bq    = (const float*)d_in[5];
    const float* Wk    = (const float*)d_in[6];
    const float* bk    = (const float*)d_in[7];
    const float* Wv    = (const float*)d_in[8];
    const float* bv    = (const float*)d_in[9];
    const float* Wp    = (const float*)d_in[10];
    const float* bp    = (const float*)d_in[11];
    float* out = (float*)d_out;

    float *Qp, *Kp, *Vp, *AOp;
    cudaGetSymbolAddress((void**)&Qp,  g_Q);
    cudaGetSymbolAddress((void**)&Kp,  g_K);
    cudaGetSymbolAddress((void**)&Vp,  g_V);
    cudaGetSymbolAddress((void**)&AOp, g_AO);

    const int M = NB * SLEN;   // 8192

    dim3 blk(256);
    dim3 gProj(EDIM / 128, M / 128, 1);          // 16 x 64

    // 1-3) Q, K, V projections (outputs tf32-rounded)
    gemm_tc<true, true><<<gProj, blk>>>(query, EDIM, Wq, EDIM, Qp, EDIM, bq, EDIM);
    gemm_tc<true, true><<<gProj, blk>>>(key,   EDIM, Wk, EDIM, Kp, EDIM, bk, EDIM);
    gemm_tc<true, true><<<gProj, blk>>>(value, EDIM, Wv, EDIM, Vp, EDIM, bv, EDIM);

    // 4) fused attention
    cudaFuncSetAttribute(attn_fused, cudaFuncAttributeMaxDynamicSharedMemorySize,
                         SMEM_WORDS * 4);
    {
        dim3 g(SLEN / 128, NB * HNUM);
        attn_fused<<<g, blk, SMEM_WORDS * 4>>>(Qp, Kp, Vp, amask, AOp);
    }

    // 5) output projection (full fp32 store)
    gemm_tc<true, false><<<gProj, blk>>>(AOp, EDIM, Wp, EDIM, out, EDIM, bp, EDIM);
}

// round 8
// speedup vs baseline: 3.4409x; 1.0087x over previous
#include <cuda_runtime.h>
#include <cstdint>

// Problem constants
#define EDIM 2048
#define HNUM 16
#define NB   4
#define SLEN 2048
#define TLEN 2048
#define DHEAD 128

#define NEG_INF (__int_as_float(0xff800000))

// Scratch (allocation-free rule: __device__ globals)
__device__ float g_Q [(size_t)NB * SLEN * EDIM];            // 64 MB (tf32-rounded)
__device__ float g_K [(size_t)NB * TLEN * EDIM];            // 64 MB (tf32-rounded)
__device__ float g_V [(size_t)NB * TLEN * EDIM];            // 64 MB (tf32-rounded)
__device__ float g_AO[(size_t)NB * SLEN * EDIM];            // 64 MB
__device__ int   g_mask_allones;

// fp32 -> tf32 round-to-nearest
__device__ __forceinline__ uint32_t f2tf(float f) {
    uint32_t u;
    asm("cvt.rna.tf32.f32 %0, %1;" : "=r"(u) : "f"(f));
    return u;
}

__device__ __forceinline__ void mma8(float& c0, float& c1, float& c2, float& c3,
                                     uint32_t a0, uint32_t a1, uint32_t a2, uint32_t a3,
                                     uint32_t b0, uint32_t b1) {
    asm volatile(
        "mma.sync.aligned.m16n8k8.row.col.f32.tf32.tf32.f32 "
        "{%0,%1,%2,%3},{%4,%5,%6,%7},{%8,%9},{%0,%1,%2,%3};"
        : "+f"(c0), "+f"(c1), "+f"(c2), "+f"(c3)
        : "r"(a0), "r"(a1), "r"(a2), "r"(a3), "r"(b0), "r"(b1));
}

__device__ __forceinline__ uint32_t smem_u32(const void* p) {
    uint32_t a;
    asm("{ .reg .u64 t; cvta.to.shared.u64 t, %1; cvt.u32.u64 %0, t; }" : "=r"(a) : "l"(p));
    return a;
}
__device__ __forceinline__ void cp16(uint32_t dst, const void* src) {
    asm volatile("cp.async.cg.shared.global [%0], [%1], 16;" :: "r"(dst), "l"(src));
}

// ---------------------------------------------------------------------------
// Tensor-core tf32 GEMM (TRANSB form only): C[m][n] = sum_k A[m][k]*B[n][k]
// 128x128 CTA tile, kChunk=16, 256 threads, double-buffered SMEM.
// RND: store C rounded to tf32 (for Q/K/V so the fused kernel can stream raw).
// ---------------------------------------------------------------------------
#define ASTRIDE 20

template<bool HAS_BIAS, bool RND>
__global__ void __launch_bounds__(256, 2)
gemm_tc(const float* __restrict__ A, int lda,
        const float* __restrict__ B, int ldb,
        float*       __restrict__ C, int ldc,
        const float* __restrict__ bias, int K)
{
    __shared__ uint32_t As[2][128 * ASTRIDE];
    __shared__ uint32_t Bs[2][128 * ASTRIDE];

    const int tid  = threadIdx.x;
    const int lane = tid & 31;
    const int warp = tid >> 5;
    const int wm   = warp & 3;
    const int wn   = warp >> 2;
    const int m0   = blockIdx.y * 128;
    const int n0   = blockIdx.x * 128;

    const int lr = tid >> 2;
    const int lk = (tid & 3) << 2;
    const int g  = lane >> 2;
    const int t  = lane & 3;

    float acc[2][8][4];
#pragma unroll
    for (int i = 0; i < 2; i++)
#pragma unroll
        for (int j = 0; j < 8; j++)
#pragma unroll
            for (int q = 0; q < 4; q++) acc[i][j][q] = 0.0f;

    const int nch = K >> 4;

#pragma unroll
    for (int i = 0; i < 2; i++) {
        int r = lr + i * 64;
        float4 v = *(const float4*)(A + (size_t)(m0 + r) * lda + lk);
        uint32_t* d = &As[0][r * ASTRIDE + lk];
        d[0] = f2tf(v.x); d[1] = f2tf(v.y); d[2] = f2tf(v.z); d[3] = f2tf(v.w);
        float4 w = *(const float4*)(B + (size_t)(n0 + r) * ldb + lk);
        uint32_t* e = &Bs[0][r * ASTRIDE + lk];
        e[0] = f2tf(w.x); e[1] = f2tf(w.y); e[2] = f2tf(w.z); e[3] = f2tf(w.w);
    }
    __syncthreads();

    int buf = 0;
    for (int ch = 0; ch < nch; ch++) {
        const bool nxt = (ch + 1 < nch);
        const int  k1  = (ch + 1) << 4;

        float4 ra[2], rb[2];
        if (nxt) {
#pragma unroll
            for (int i = 0; i < 2; i++) {
                int r = lr + i * 64;
                ra[i] = *(const float4*)(A + (size_t)(m0 + r) * lda + k1 + lk);
                rb[i] = *(const float4*)(B + (size_t)(n0 + r) * ldb + k1 + lk);
            }
        }

        const uint32_t* as = As[buf];
        const uint32_t* bs = Bs[buf];
#pragma unroll
        for (int ks = 0; ks < 16; ks += 8) {
            uint32_t af[2][4];
#pragma unroll
            for (int mi = 0; mi < 2; mi++) {
                int row = wm * 32 + mi * 16 + g;
                af[mi][0] = as[row * ASTRIDE + ks + t];
                af[mi][1] = as[(row + 8) * ASTRIDE + ks + t];
                af[mi][2] = as[row * ASTRIDE + ks + t + 4];
                af[mi][3] = as[(row + 8) * ASTRIDE + ks + t + 4];
            }
            uint32_t bf[8][2];
#pragma unroll
            for (int ni = 0; ni < 8; ni++) {
                int nn = wn * 64 + ni * 8 + g;
                bf[ni][0] = bs[nn * ASTRIDE + ks + t];
                bf[ni][1] = bs[nn * ASTRIDE + ks + t + 4];
            }
#pragma unroll
            for (int mi = 0; mi < 2; mi++)
#pragma unroll
                for (int ni = 0; ni < 8; ni++)
                    mma8(acc[mi][ni][0], acc[mi][ni][1], acc[mi][ni][2], acc[mi][ni][3],
                         af[mi][0], af[mi][1], af[mi][2], af[mi][3],
                         bf[ni][0], bf[ni][1]);
        }

        if (nxt) {
            uint32_t* asn = As[buf ^ 1];
            uint32_t* bsn = Bs[buf ^ 1];
#pragma unroll
            for (int i = 0; i < 2; i++) {
                int r = lr + i * 64;
                uint32_t* d = &asn[r * ASTRIDE + lk];
                d[0] = f2tf(ra[i].x); d[1] = f2tf(ra[i].y);
                d[2] = f2tf(ra[i].z); d[3] = f2tf(ra[i].w);
                uint32_t* e = &bsn[r * ASTRIDE + lk];
                e[0] = f2tf(rb[i].x); e[1] = f2tf(rb[i].y);
                e[2] = f2tf(rb[i].z); e[3] = f2tf(rb[i].w);
            }
        }
        __syncthreads();
        buf ^= 1;
    }

#pragma unroll
    for (int mi = 0; mi < 2; mi++) {
#pragma unroll
        for (int rr = 0; rr < 2; rr++) {
            int m = m0 + wm * 32 + mi * 16 + g + rr * 8;
#pragma unroll
            for (int ni = 0; ni < 8; ni++) {
                int n = n0 + wn * 64 + ni * 8 + 2 * t;
                float v0 = acc[mi][ni][rr * 2 + 0];
                float v1 = acc[mi][ni][rr * 2 + 1];
                if (HAS_BIAS) { v0 += bias[n]; v1 += bias[n + 1]; }
                if (RND) {
                    v0 = __uint_as_float(f2tf(v0));
                    v1 = __uint_as_float(f2tf(v1));
                }
                *(float2*)(C + (size_t)m * ldc + n) = make_float2(v0, v1);
            }
        }
    }
}

// ---------------------------------------------------------------------------
// Mask scan: set g_mask_allones=0 if any mask element is zero.
// ---------------------------------------------------------------------------
__global__ void mask_reset() { g_mask_allones = 1; }

__global__ void __launch_bounds__(512)
mask_scan(const int* __restrict__ mask)
{
    const int n4 = (SLEN * TLEN) / 4;
    int i = blockIdx.x * 512 + threadIdx.x;
    int bad = 0;
    for (; i < n4; i += gridDim.x * 512) {
        int4 v = ((const int4*)mask)[i];
        if (!(v.x && v.y && v.z && v.w)) bad = 1;
    }
    if (bad) g_mask_allones = 0;
}

// ---------------------------------------------------------------------------
// Fused flash attention: per CTA 128 query rows; stream K/V in T-tiles of 64.
// 512 threads = 16 warps: wm=warp>>1 (16 rows each), wn=warp&1.
//   S = Q K^T * scale (+mask) ; online softmax ; O += P V ; AO = O / l
// ---------------------------------------------------------------------------
#define BT 64
#define LDQ 132
#define LDK 132
#define LDV 136
#define LDP 68
#define OFF_Q 0
#define OFF_K 16896
#define OFF_V 25344
#define VBUFW 8704
#define OFF_P 42752
#define OFF_RM 51456
#define OFF_RS 51712
#define SMEM_WORDS 51968

__global__ void __launch_bounds__(512, 1)
attn_fused(const float* __restrict__ Q, const float* __restrict__ K,
           const float* __restrict__ V, const int* __restrict__ mask,
           float* __restrict__ AO)
{
    extern __shared__ uint32_t sm[];
    const uint32_t smb = smem_u32(sm);

    const int tid  = threadIdx.x;
    const int lane = tid & 31;
    const int warp = tid >> 5;       // 0..15
    const int wm   = warp >> 1;      // 0..7  -> 16 rows each
    const int wn   = warp & 1;       // 0..1
    const int g    = lane >> 2;
    const int t    = lane & 3;
    const int s0   = blockIdx.x * 128;
    const int bh   = blockIdx.y;
    const int zn   = bh >> 4, zh = bh & 15;
    const float scale = 0.08838834764831845f;   // 1/sqrt(128)
    const bool use_mask = (g_mask_allones == 0);

    const size_t qbase  = ((size_t)zn * SLEN + s0) * EDIM + (size_t)zh * DHEAD;
    const size_t kvbase = ((size_t)zn * TLEN) * EDIM + (size_t)zh * DHEAD;

    // ---- prologue: Q (once), K0, V0 ----
#pragma unroll
    for (int i = 0; i < 8; i++) {
        int idx = tid + i * 512;
        int r = idx >> 5, c = (idx & 31) << 2;
        cp16(smb + (OFF_Q + r * LDQ + c) * 4, Q + qbase + (size_t)r * EDIM + c);
    }
#pragma unroll
    for (int i = 0; i < 4; i++) {
        int idx = tid + i * 512;
        int r = idx >> 5, c = (idx & 31) << 2;
        cp16(smb + (OFF_K + r * LDK + c) * 4, K + kvbase + (size_t)r * EDIM + c);
    }
#pragma unroll
    for (int i = 0; i < 4; i++) {
        int idx = tid + i * 512;
        int r = idx >> 5, c = (idx & 31) << 2;
        cp16(smb + (OFF_V + r * LDV + c) * 4, V + kvbase + (size_t)r * EDIM + c);
    }
    asm volatile("cp.async.commit_group;");

    float Oa[8][4];
#pragma unroll
    for (int j = 0; j < 8; j++)
#pragma unroll
        for (int q = 0; q < 4; q++) Oa[j][q] = 0.0f;
    float m_run[2], l_run[2];
#pragma unroll
    for (int s = 0; s < 2; s++) { m_run[s] = NEG_INF; l_run[s] = 0.0f; }

    const int arow0 = wm * 16;

    for (int j = 0; j < TLEN / BT; j++) {
        asm volatile("cp.async.wait_group 0;" ::: "memory");
        __syncthreads();
        const int vb = j & 1;
        const int t0 = j * BT;

        // ---- S = Q K^T ----
        float Sa[4][4];
#pragma unroll
        for (int n = 0; n < 4; n++)
#pragma unroll
            for (int q = 0; q < 4; q++) Sa[n][q] = 0.0f;

#pragma unroll
        for (int ks = 0; ks < DHEAD; ks += 8) {
            uint32_t af[4];
            {
                int row = arow0 + g;
                af[0] = sm[OFF_Q + row * LDQ + ks + t];
                af[1] = sm[OFF_Q + (row + 8) * LDQ + ks + t];
                af[2] = sm[OFF_Q + row * LDQ + ks + t + 4];
                af[3] = sm[OFF_Q + (row + 8) * LDQ + ks + t + 4];
            }
            uint32_t bf[4][2];
#pragma unroll
            for (int ni = 0; ni < 4; ni++) {
                int n = wn * 32 + ni * 8 + g;
                bf[ni][0] = sm[OFF_K + n * LDK + ks + t];
                bf[ni][1] = sm[OFF_K + n * LDK + ks + t + 4];
            }
#pragma unroll
            for (int ni = 0; ni < 4; ni++)
                mma8(Sa[ni][0], Sa[ni][1], Sa[ni][2], Sa[ni][3],
                     af[0], af[1], af[2], af[3], bf[ni][0], bf[ni][1]);
        }

        // ---- scale + optional mask ----
#pragma unroll
        for (int ni = 0; ni < 4; ni++)
#pragma unroll
            for (int q = 0; q < 4; q++) Sa[ni][q] *= scale;

        if (use_mask) {
#pragma unroll
            for (int rr = 0; rr < 2; rr++) {
                int srow = s0 + arow0 + rr * 8 + g;
#pragma unroll
                for (int ni = 0; ni < 4; ni++)
#pragma unroll
                    for (int q = 0; q < 2; q++) {
                        int col = t0 + wn * 32 + ni * 8 + 2 * t + q;
                        if (__ldg(&mask[(size_t)col * SLEN + srow]) == 0)
                            Sa[ni][rr * 2 + q] = NEG_INF;
                    }
            }
        }

        // ---- row max ----
#pragma unroll
        for (int rr = 0; rr < 2; rr++) {
            float mx = NEG_INF;
#pragma unroll
            for (int ni = 0; ni < 4; ni++) {
                mx = fmaxf(mx, Sa[ni][rr * 2]);
                mx = fmaxf(mx, Sa[ni][rr * 2 + 1]);
            }
            mx = fmaxf(mx, __shfl_xor_sync(0xffffffffu, mx, 1));
            mx = fmaxf(mx, __shfl_xor_sync(0xffffffffu, mx, 2));
            if (t == 0) {
                int r = arow0 + rr * 8 + g;
                *(float*)&sm[OFF_RM + r * 2 + wn] = mx;
            }
        }
        __syncthreads();

        float m_new[2], alpha[2];
#pragma unroll
        for (int rr = 0; rr < 2; rr++) {
            int r = arow0 + rr * 8 + g;
            float tm = fmaxf(*(float*)&sm[OFF_RM + r * 2],
                             *(float*)&sm[OFF_RM + r * 2 + 1]);
            m_new[rr] = fmaxf(m_run[rr], tm);
            alpha[rr] = __expf(m_run[rr] - m_new[rr]);
            m_run[rr] = m_new[rr];
        }

        // ---- P = exp(S - m), write to SMEM, row sums ----
#pragma unroll
        for (int rr = 0; rr < 2; rr++) {
            int r = arow0 + rr * 8 + g;
            float sum = 0.0f;
#pragma unroll
            for (int ni = 0; ni < 4; ni++) {
                float p0 = __expf(Sa[ni][rr * 2]     - m_new[rr]);
                float p1 = __expf(Sa[ni][rr * 2 + 1] - m_new[rr]);
                sum += p0 + p1;
                uint2 pp = make_uint2(f2tf(p0), f2tf(p1));
                *(uint2*)&sm[OFF_P + r * LDP + wn * 32 + ni * 8 + 2 * t] = pp;
            }
            sum += __shfl_xor_sync(0xffffffffu, sum, 1);
            sum += __shfl_xor_sync(0xffffffffu, sum, 2);
            if (t == 0) *(float*)&sm[OFF_RS + r * 2 + wn] = sum;
        }
        __syncthreads();

#pragma unroll
        for (int rr = 0; rr < 2; rr++) {
            int r = arow0 + rr * 8 + g;
            float ts = *(float*)&sm[OFF_RS + r * 2] + *(float*)&sm[OFF_RS + r * 2 + 1];
            l_run[rr] = l_run[rr] * alpha[rr] + ts;
        }
        // rescale O
#pragma unroll
        for (int ni = 0; ni < 8; ni++)
#pragma unroll
            for (int q = 0; q < 4; q++)
                Oa[ni][q] *= alpha[q >> 1];

        // ---- prefetch next K/V tile (overlaps with PV) ----
        if (j + 1 < TLEN / BT) {
            const int tn = (j + 1) * BT;
            const int vn = vb ^ 1;
#pragma unroll
            for (int i = 0; i < 4; i++) {
                int idx = tid + i * 512;
                int r = idx >> 5, c = (idx & 31) << 2;
                cp16(smb + (OFF_K + r * LDK + c) * 4,
                     K + kvbase + (size_t)(tn + r) * EDIM + c);
            }
#pragma unroll
            for (int i = 0; i < 4; i++) {
                int idx = tid + i * 512;
                int r = idx >> 5, c = (idx & 31) << 2;
                cp16(smb + (OFF_V + vn * VBUFW + r * LDV + c) * 4,
                     V + kvbase + (size_t)(tn + r) * EDIM + c);
            }
            asm volatile("cp.async.commit_group;");
        }

        // ---- O += P V ----
        const uint32_t* vs = &sm[OFF_V + vb * VBUFW];
#pragma unroll
        for (int ks = 0; ks < BT; ks += 8) {
            uint32_t af[4];
            {
                int row = arow0 + g;
                af[0] = sm[OFF_P + row * LDP + ks + t];
                af[1] = sm[OFF_P + (row + 8) * LDP + ks + t];
                af[2] = sm[OFF_P + row * LDP + ks + t + 4];
                af[3] = sm[OFF_P + (row + 8) * LDP + ks + t + 4];
            }
            uint32_t bf[8][2];
#pragma unroll
            for (int ni = 0; ni < 8; ni++) {
                int n = wn * 64 + ni * 8 + g;
                bf[ni][0] = vs[(ks + t) * LDV + n];
                bf[ni][1] = vs[(ks + t + 4) * LDV + n];
            }
#pragma unroll
            for (int ni = 0; ni < 8; ni++)
                mma8(Oa[ni][0], Oa[ni][1], Oa[ni][2], Oa[ni][3],
                     af[0], af[1], af[2], af[3], bf[ni][0], bf[ni][1]);
        }
    }

    // ---- epilogue: AO = O / l ----
#pragma unroll
    for (int rr = 0; rr < 2; rr++) {
        float inv = 1.0f / l_run[rr];
        int r = arow0 + rr * 8 + g;
#pragma unroll
        for (int ni = 0; ni < 8; ni++) {
            int col = wn * 64 + ni * 8 + 2 * t;
            float2 o = make_float2(Oa[ni][rr * 2] * inv,
                                   Oa[ni][rr * 2 + 1] * inv);
            *(float2*)(AO + qbase + (size_t)r * EDIM + col) = o;
        }
    }
}

// ---------------------------------------------------------------------------
// Host launcher
// ---------------------------------------------------------------------------
extern "C" void kernel_launch(void* const* d_in, const int* in_sizes, int n_in,
                              void* d_out, int out_size)
{
    const float* query = (const float*)d_in[0];
    const float* key   = (const float*)d_in[1];
    const float* value = (const float*)d_in[2];
    const int*   amask = (const int*)  d_in[3];
    const float* Wq    = (const float*)d_in[4];
    const float* bq    = (const float*)d_in[5];
    const float* Wk    = (const float*)d_in[6];
    const float* bk    = (const float*)d_in[7];
    const float* Wv    = (const float*)d_in[8];
    const float* bv    = (const float*)d_in[9];
    const float* Wp    = (const float*)d_in[10];
    const float* bp    = (const float*)d_in[11];
    float* out = (float*)d_out;

    float *Qp, *Kp, *Vp, *AOp;
    cudaGetSymbolAddress((void**)&Qp,  g_Q);
    cudaGetSymbolAddress((void**)&Kp,  g_K);
    cudaGetSymbolAddress((void**)&Vp,  g_V);
    cudaGetSymbolAddress((void**)&AOp, g_AO);

    const int M = NB * SLEN;   // 8192

    dim3 blk(256);
    dim3 gProj(EDIM / 128, M / 128, 1);          // 16 x 64

    // 0) mask all-ones scan (overlaps nothing; ~10us)
    mask_reset<<<1, 1>>>();
    mask_scan<<<1024, 512>>>(amask);

    // 1-3) Q, K, V projections (outputs tf32-rounded)
    gemm_tc<true, true><<<gProj, blk>>>(query, EDIM, Wq, EDIM, Qp, EDIM, bq, EDIM);
    gemm_tc<true, true><<<gProj, blk>>>(key,   EDIM, Wk, EDIM, Kp, EDIM, bk, EDIM);
    gemm_tc<true, true><<<gProj, blk>>>(value, EDIM, Wv, EDIM, Vp, EDIM, bv, EDIM);

    // 4) fused attention (512 threads, 16 warps)
    cudaFuncSetAttribute(attn_fused, cudaFuncAttributeMaxDynamicSharedMemorySize,
                         SMEM_WORDS * 4);
    {
        dim3 g(SLEN / 128, NB * HNUM);
        attn_fused<<<g, dim3(512), SMEM_WORDS * 4>>>(Qp, Kp, Vp, amask, AOp);
    }

    // 5) output projection (full fp32 store)
    gemm_tc<true, false><<<gProj, blk>>>(AOp, EDIM, Wp, EDIM, out, EDIM, bp, EDIM);
}